// round 5
// baseline (speedup 1.0000x reference)
#include <cuda_runtime.h>
#include <cuda_bf16.h>
#include <math.h>

// Problem sizes (fixed by the reference)
#define BB 64      // batch
#define TT 32      // timesteps
#define EE 512     // embed dim
#define HH 512     // hidden
#define H4 2048    // 4*H
#define VV 10000   // vocab

#define KSPLIT 8   // K-split for the recurrence GEMM

// ---------------- scratch (device globals: allocation-free) ----------------
__device__ __align__(16) float g_X[TT * BB * EE];        // [T][B][E]
__device__ __align__(16) float g_xproj[TT * BB * H4];    // [T][B][4H]
__device__ __align__(16) float g_hseq[TT * BB * HH];     // [T][B][H]
__device__ __align__(16) float g_h[BB * HH];
__device__ __align__(16) float g_c[BB * HH];
__device__ __align__(16) float g_gpart[KSPLIT * BB * H4];
__device__ int g_cap64;

// ---------------- captions dtype detection (int32 vs int64) ----------------
// jnp int64 request may silently become int32 without jax x64. For int64
// (values in [0,10000)) every high 32-bit word is 0; for int32 the odd words
// are random caption ids. Reads only the first 2048 int32 words, which is
// within the buffer for either dtype.
__global__ void detect_cap_kernel(const int* __restrict__ cap32) {
    if (threadIdx.x == 0 && blockIdx.x == 0) {
        int acc = 0;
        for (int i = 0; i < 256; i++) acc |= cap32[2 * i + 1];
        g_cap64 = (acc == 0) ? 1 : 0;
    }
}

// ---------------- init h0/c0 = 0 ----------------
__global__ void zero_state_kernel() {
    int i = blockIdx.x * blockDim.x + threadIdx.x;
    if (i < BB * HH) { g_h[i] = 0.0f; g_c[i] = 0.0f; }
}

// ---------------- build X ----------------
__global__ void build_x_kernel(const float* __restrict__ feat,
                               const void* __restrict__ cap,
                               const float* __restrict__ embW) {
    int row = blockIdx.x;            // row = t*B + b
    int t = row >> 6;
    int b = row & 63;
    const float* src;
    if (t == 0) {
        src = feat + (size_t)b * EE;
    } else {
        long long idx;
        if (g_cap64) idx = ((const long long*)cap)[b * TT + t];
        else         idx = (long long)((const int*)cap)[b * TT + t];
        src = embW + (size_t)idx * EE;
    }
    float4* dst = (float4*)(g_X + (size_t)row * EE);
    const float4* s4 = (const float4*)src;
    for (int i = threadIdx.x; i < EE / 4; i += blockDim.x) dst[i] = s4[i];
}

// ---------------- SGEMM NT: C[M,N] = A[M,K] * B[N,K]^T (+ biases) ----------
// asel: 0 -> A = g_X, 1 -> A = g_hseq (device scratch selection)
// mode: 0 -> C row-major [m*N+n]; 1 -> C[(b*T+t)*N+n] with m = t*64+b
#define BM 128
#define BN 128
#define BK 16

__global__ __launch_bounds__(256) void sgemm_nt_kernel(
    int asel, const float* __restrict__ Bm,
    const float* __restrict__ bias1, const float* __restrict__ bias2,
    float* __restrict__ C, int M, int N, int K, int mode)
{
    const float* __restrict__ A = (asel == 0) ? g_X : g_hseq;

    // Row stride BM+4 = 132 floats = 528 bytes: multiple of 16B, so float4
    // reads at &As[buf][kk][8*t] are always 16B-aligned.
    __shared__ float As[2][BK][BM + 4];
    __shared__ float Bs[2][BK][BN + 4];

    const int tid = threadIdx.x;
    const int bm = blockIdx.y * BM;
    const int bn = blockIdx.x * BN;

    const int lr = tid >> 2;           // 0..63
    const int lk = (tid & 3) << 2;     // 0,4,8,12

    const int tx = tid & 15;
    const int ty = tid >> 4;

    float acc[8][8];
#pragma unroll
    for (int i = 0; i < 8; i++)
#pragma unroll
        for (int j = 0; j < 8; j++) acc[i][j] = 0.0f;

    float4 ra0, ra1, rb0, rb1;
    const float4 z4 = make_float4(0.f, 0.f, 0.f, 0.f);

#define FETCH(K0)                                                              \
    do {                                                                       \
        ra0 = *(const float4*)(A + (size_t)(bm + lr) * K + (K0) + lk);         \
        ra1 = *(const float4*)(A + (size_t)(bm + lr + 64) * K + (K0) + lk);    \
        int r0_ = bn + lr, r1_ = bn + lr + 64;                                 \
        rb0 = (r0_ < N) ? *(const float4*)(Bm + (size_t)r0_ * K + (K0) + lk) : z4; \
        rb1 = (r1_ < N) ? *(const float4*)(Bm + (size_t)r1_ * K + (K0) + lk) : z4; \
    } while (0)

#define STAGE(BUF)                                                             \
    do {                                                                       \
        As[BUF][lk + 0][lr] = ra0.x; As[BUF][lk + 1][lr] = ra0.y;              \
        As[BUF][lk + 2][lr] = ra0.z; As[BUF][lk + 3][lr] = ra0.w;              \
        As[BUF][lk + 0][lr + 64] = ra1.x; As[BUF][lk + 1][lr + 64] = ra1.y;    \
        As[BUF][lk + 2][lr + 64] = ra1.z; As[BUF][lk + 3][lr + 64] = ra1.w;    \
        Bs[BUF][lk + 0][lr] = rb0.x; Bs[BUF][lk + 1][lr] = rb0.y;              \
        Bs[BUF][lk + 2][lr] = rb0.z; Bs[BUF][lk + 3][lr] = rb0.w;              \
        Bs[BUF][lk + 0][lr + 64] = rb1.x; Bs[BUF][lk + 1][lr + 64] = rb1.y;    \
        Bs[BUF][lk + 2][lr + 64] = rb1.z; Bs[BUF][lk + 3][lr + 64] = rb1.w;    \
    } while (0)

    FETCH(0);
    STAGE(0);
    __syncthreads();

    const int nk = K / BK;
    for (int kt = 0; kt < nk; kt++) {
        if (kt + 1 < nk) FETCH((kt + 1) * BK);
        const int buf = kt & 1;
#pragma unroll
        for (int kk = 0; kk < BK; kk++) {
            float4 a0 = *(const float4*)&As[buf][kk][ty * 8];
            float4 a1 = *(const float4*)&As[buf][kk][ty * 8 + 4];
            float4 b0 = *(const float4*)&Bs[buf][kk][tx * 8];
            float4 b1 = *(const float4*)&Bs[buf][kk][tx * 8 + 4];
            float av[8] = {a0.x, a0.y, a0.z, a0.w, a1.x, a1.y, a1.z, a1.w};
            float bv[8] = {b0.x, b0.y, b0.z, b0.w, b1.x, b1.y, b1.z, b1.w};
#pragma unroll
            for (int i = 0; i < 8; i++)
#pragma unroll
                for (int j = 0; j < 8; j++) acc[i][j] += av[i] * bv[j];
        }
        if (kt + 1 < nk) {
            __syncthreads();
            STAGE((kt + 1) & 1);
            __syncthreads();
        }
    }

#pragma unroll
    for (int i = 0; i < 8; i++) {
        int m = bm + ty * 8 + i;
        int t = m >> 6;
        int b = m & 63;
#pragma unroll
        for (int j = 0; j < 8; j++) {
            int n = bn + tx * 8 + j;
            if (n < N) {
                float v = acc[i][j];
                if (bias1) v += bias1[n];
                if (bias2) v += bias2[n];
                if (mode == 0) C[(size_t)m * N + n] = v;
                else           C[(size_t)(b * TT + t) * N + n] = v;
            }
        }
    }
#undef FETCH
#undef STAGE
}

// ---------------- LSTM stage 1: K-split partial GEMM -----------------------
// gpart[s][b][g] = sum_{k in chunk s} h[b][k] * W_hh[g][k]
// grid (16, KSPLIT), block 256. Micro-tile 8 batches x 4 gates.
__global__ __launch_bounds__(256) void lstm_part_kernel(const float* __restrict__ Whh)
{
    const int g0 = blockIdx.x * 128;
    const int k0 = blockIdx.y * (HH / KSPLIT);   // 64-wide K chunk
    const int tid = threadIdx.x;
    const int tgx = tid & 31;
    const int tby = tid >> 5;

    // FIX (R3): row strides must be multiples of 4 floats (16B) because the
    // compute loop reads these via float4. Previous +2 padding gave strides
    // 66/130 floats -> 8-byte-misaligned float4 addresses for odd kk ->
    // "misaligned address" trap. Strides are now 68/132 (16B multiples).
    __shared__ float hs[16][BB + 4];
    __shared__ float ws[16][128 + 4];

    float acc[8][4];
#pragma unroll
    for (int i = 0; i < 8; i++)
#pragma unroll
        for (int j = 0; j < 4; j++) acc[i][j] = 0.0f;

    for (int ks = 0; ks < HH / KSPLIT; ks += 16) {
        for (int i = tid; i < 16 * BB; i += 256) {
            int b = i >> 4, kk = i & 15;
            hs[kk][b] = g_h[b * HH + k0 + ks + kk];
        }
        for (int i = tid; i < 16 * 128; i += 256) {
            int g = i >> 4, kk = i & 15;
            ws[kk][g] = Whh[(size_t)(g0 + g) * HH + k0 + ks + kk];
        }
        __syncthreads();
#pragma unroll
        for (int kk = 0; kk < 16; kk++) {
            float4 wv = *(const float4*)&ws[kk][tgx * 4];
            float4 h0 = *(const float4*)&hs[kk][tby * 8];
            float4 h1 = *(const float4*)&hs[kk][tby * 8 + 4];
            float hv[8] = {h0.x, h0.y, h0.z, h0.w, h1.x, h1.y, h1.z, h1.w};
            float wf[4] = {wv.x, wv.y, wv.z, wv.w};
#pragma unroll
            for (int i = 0; i < 8; i++)
#pragma unroll
                for (int j = 0; j < 4; j++) acc[i][j] += hv[i] * wf[j];
        }
        __syncthreads();
    }

#pragma unroll
    for (int i = 0; i < 8; i++) {
        size_t base = ((size_t)blockIdx.y * BB + (tby * 8 + i)) * H4 + g0 + tgx * 4;
        *(float4*)&g_gpart[base] = make_float4(acc[i][0], acc[i][1], acc[i][2], acc[i][3]);
    }
}

// ---------------- LSTM stage 2: reduce partials + gates + state update -----
__global__ void lstm_update_kernel(int t, int use_part)
{
    int idx = blockIdx.x * blockDim.x + threadIdx.x;
    if (idx >= BB * HH) return;
    int b = idx >> 9;
    int u = idx & 511;

    const float* xp = g_xproj + ((size_t)(t * BB + b)) * H4;
    float gi = xp[u];
    float gf = xp[HH + u];
    float gg = xp[2 * HH + u];
    float go = xp[3 * HH + u];

    if (use_part) {
#pragma unroll
        for (int s = 0; s < KSPLIT; s++) {
            const float* p = g_gpart + ((size_t)s * BB + b) * H4;
            gi += p[u];
            gf += p[HH + u];
            gg += p[2 * HH + u];
            go += p[3 * HH + u];
        }
    }

    float i_g = 1.0f / (1.0f + expf(-gi));
    float f_g = 1.0f / (1.0f + expf(-gf));
    float g_g = tanhf(gg);
    float o_g = 1.0f / (1.0f + expf(-go));

    float c = f_g * g_c[idx] + i_g * g_g;
    float h = o_g * tanhf(c);
    g_c[idx] = c;
    g_h[idx] = h;
    g_hseq[((size_t)(t * BB + b)) * HH + u] = h;
}

// ---------------- launch ----------------
extern "C" void kernel_launch(void* const* d_in, const int* in_sizes, int n_in,
                              void* d_out, int out_size)
{
    const float* features = (const float*)d_in[0];
    const void*  captions = d_in[1];                 // int32 or int64, detected
    const float* embed_W  = (const float*)d_in[2];
    const float* W_ih     = (const float*)d_in[3];
    const float* W_hh     = (const float*)d_in[4];
    const float* b_ih     = (const float*)d_in[5];
    const float* b_hh     = (const float*)d_in[6];
    const float* fc_W     = (const float*)d_in[7];
    const float* fc_b     = (const float*)d_in[8];
    float* out = (float*)d_out;

    // Resolve device address of the g_xproj scratch once (host-side symbol
    // lookup; allocation-free and graph-safe).
    static float* xproj_ptr = nullptr;
    if (!xproj_ptr) {
        void* p = nullptr;
        cudaGetSymbolAddress(&p, g_xproj);
        xproj_ptr = (float*)p;
    }

    detect_cap_kernel<<<1, 32>>>((const int*)captions);
    zero_state_kernel<<<(BB * HH + 255) / 256, 256>>>();
    build_x_kernel<<<TT * BB, 128>>>(features, captions, embed_W);

    // x_proj = X @ W_ih^T + b_ih + b_hh   [T*B, 4H]
    sgemm_nt_kernel<<<dim3(H4 / BN, (TT * BB) / BM), 256>>>(
        0, W_ih, b_ih, b_hh, xproj_ptr, TT * BB, H4, EE, 0);

    for (int t = 0; t < TT; t++) {
        if (t > 0) lstm_part_kernel<<<dim3(H4 / 128, KSPLIT), 256>>>(W_hh);
        lstm_update_kernel<<<(BB * HH + 255) / 256, 256>>>(t, t > 0 ? 1 : 0);
    }

    // logits: out[b][t][v] = h_seq[t][b] . fc_W[v] + fc_b[v]
    sgemm_nt_kernel<<<dim3((VV + BN - 1) / BN, (TT * BB) / BM), 256>>>(
        1, fc_W, fc_b, nullptr, out, TT * BB, VV, HH, 1);
}